// round 8
// baseline (speedup 1.0000x reference)
#include <cuda_runtime.h>
#include <math.h>
#include <stdint.h>

#define B_ 8
#define N_ 1024
#define C_ 768
#define H_ 12
#define D_ 64
#define BH_ (B_*H_)

// Scratch (device globals — no allocation allowed)
__device__ float g_q [BH_*N_*D_];   // [B,H,N,D]
__device__ float g_k [BH_*N_*D_];
__device__ float g_v [BH_*N_*D_];
__device__ float g_ao[B_*N_*C_];    // attention output in [B,N,C]

// ---------------------------------------------------------------------------
// tf32 helpers
// ---------------------------------------------------------------------------
__device__ __forceinline__ uint32_t f2tf(float f) {
    uint32_t u;
    asm("cvt.rna.tf32.f32 %0, %1;" : "=r"(u) : "f"(f));
    return u;
}

__device__ __forceinline__ void mma8(float* c, const uint32_t* a, const uint32_t* b) {
    asm volatile(
        "mma.sync.aligned.m16n8k8.row.col.f32.tf32.tf32.f32 "
        "{%0,%1,%2,%3},{%4,%5,%6,%7},{%8,%9},{%0,%1,%2,%3};"
        : "+f"(c[0]), "+f"(c[1]), "+f"(c[2]), "+f"(c[3])
        : "r"(a[0]), "r"(a[1]), "r"(a[2]), "r"(a[3]), "r"(b[0]), "r"(b[1]));
}

// ---------------------------------------------------------------------------
// tf32 GEMM: Y[m,c] = sum_k A[m,k] * W[c,k]
// Block 128x128, BK=16, 256 threads = 8 warps (2x4), warp tile 64x32.
// Paired+group-XOR smem layout: every fragment is one conflict-free LDS.64.
//   word(row,k) = row*16 + ((k>>3)^((row>>2)&1))*8 + (k&3)*2 + ((k>>2)&1)
// MODE 0: scatter into g_q/g_k/g_v;  MODE 1: A := g_ao, row-major store.
// ---------------------------------------------------------------------------
template<int MODE>
__global__ __launch_bounds__(256)
void gemm_tf32(const float* __restrict__ A, const float* __restrict__ W,
               float* __restrict__ Y, int M, int Ncol, int K)
{
    __shared__ uint32_t As[128*16];
    __shared__ uint32_t Ws[128*16];

    const int tid  = threadIdx.x;
    const int warp = tid >> 5, lane = tid & 31;
    const int g    = lane >> 2, tig = lane & 3;
    const int wm   = (warp >> 2) * 64;
    const int wn   = (warp & 3)  * 32;
    const int bm   = blockIdx.y * 128;
    const int bn   = blockIdx.x * 128;

    if (MODE == 1) A = g_ao;

    const int lr = tid >> 1;        // 0..127
    const int lg = tid & 1;         // logical group (cols lg*8 .. +7)
    const int pg = lg ^ ((lr >> 2) & 1);   // physical group after XOR

    const float* Ap = A + (size_t)(bm + lr) * K + lg*8;
    const float* Wp = W + (size_t)(bn + lr) * K + lg*8;

    // hoisted fragment base offsets (words)
    const int g2   = (g >> 2) & 1;
    const int pgA0 = g2 * 8;            // physical group for kk=0
    const int pgA8 = (1 ^ g2) * 8;      // physical group for kk=8
    const uint32_t* a_base = As + (wm + g)*16 + tig*2;
    const uint32_t* b_base = Ws + (wn + g)*16 + tig*2;

    float acc[4][4][4];
    #pragma unroll
    for (int i = 0; i < 4; i++)
        #pragma unroll
        for (int j = 0; j < 4; j++)
            #pragma unroll
            for (int e = 0; e < 4; e++) acc[i][j][e] = 0.f;

    float4 ra0 = *(const float4*)Ap;
    float4 ra1 = *(const float4*)(Ap + 4);
    float4 rw0 = *(const float4*)Wp;
    float4 rw1 = *(const float4*)(Wp + 4);

    for (int k0 = 0; k0 < K; k0 += 16) {
        __syncthreads();
        {
            // words [pg*8 .. +7] = j-order 0,4,1,5,2,6,3,7
            uint32_t* da = As + lr*16 + pg*8;
            uint32_t* dw = Ws + lr*16 + pg*8;
            *(uint4*)(da)     = make_uint4(f2tf(ra0.x), f2tf(ra1.x), f2tf(ra0.y), f2tf(ra1.y));
            *(uint4*)(da + 4) = make_uint4(f2tf(ra0.z), f2tf(ra1.z), f2tf(ra0.w), f2tf(ra1.w));
            *(uint4*)(dw)     = make_uint4(f2tf(rw0.x), f2tf(rw1.x), f2tf(rw0.y), f2tf(rw1.y));
            *(uint4*)(dw + 4) = make_uint4(f2tf(rw0.z), f2tf(rw1.z), f2tf(rw0.w), f2tf(rw1.w));
        }
        __syncthreads();

        if (k0 + 16 < K) {
            Ap += 16; Wp += 16;
            ra0 = *(const float4*)Ap;
            ra1 = *(const float4*)(Ap + 4);
            rw0 = *(const float4*)Wp;
            rw1 = *(const float4*)(Wp + 4);
        }

        #pragma unroll
        for (int kk = 0; kk < 2; kk++) {
            const int pgk = kk ? pgA8 : pgA0;
            uint32_t af[4][4];
            #pragma unroll
            for (int mf = 0; mf < 4; mf++) {
                uint2 lo = *(const uint2*)(a_base + mf*256 + pgk);        // row r0
                uint2 hi = *(const uint2*)(a_base + mf*256 + 128 + pgk);  // row r0+8
                af[mf][0] = lo.x; af[mf][1] = hi.x;
                af[mf][2] = lo.y; af[mf][3] = hi.y;
            }
            uint32_t bf[4][2];
            #pragma unroll
            for (int nf = 0; nf < 4; nf++) {
                uint2 bb = *(const uint2*)(b_base + nf*128 + pgk);
                bf[nf][0] = bb.x; bf[nf][1] = bb.y;
            }
            #pragma unroll
            for (int mf = 0; mf < 4; mf++)
                #pragma unroll
                for (int nf = 0; nf < 4; nf++)
                    mma8(acc[mf][nf], af[mf], bf[nf]);
        }
    }

    // epilogue
    #pragma unroll
    for (int mf = 0; mf < 4; mf++) {
        #pragma unroll
        for (int rr = 0; rr < 2; rr++) {
            const int m = bm + wm + mf*16 + g + rr*8;
            const int b = m >> 10;
            const int n = m & 1023;
            #pragma unroll
            for (int nf = 0; nf < 4; nf++) {
                const int c = bn + wn + nf*8 + 2*tig;
                float2 v2;
                v2.x = acc[mf][nf][rr*2 + 0];
                v2.y = acc[mf][nf][rr*2 + 1];
                if (MODE == 1) {
                    *(float2*)&Y[(size_t)m * Ncol + c] = v2;
                } else {
                    const int s = c / C_;
                    const int w = c - s * C_;
                    const int h = w >> 6;
                    const int d = w & 63;
                    const int idx = ((b*H_ + h)*N_ + n)*D_ + d;
                    if (s == 0)      *(float2*)&g_q[idx] = v2;
                    else if (s == 1) *(float2*)&g_k[idx] = v2;
                    else             *(float2*)&g_v[idx] = v2;
                }
            }
        }
    }
}

// ---------------------------------------------------------------------------
// Per-head LayerNorm over D=64. q rows also *SCALE (=1/8).
// ---------------------------------------------------------------------------
__global__ __launch_bounds__(256)
void ln_kernel()
{
    const int warp = (blockIdx.x * blockDim.x + threadIdx.x) >> 5;
    const int lane = threadIdx.x & 31;
    const int nrows = BH_ * N_;
    if (warp >= 2 * nrows) return;

    float* buf  = (warp < nrows) ? g_q : g_k;
    const float scale = (warp < nrows) ? 0.125f : 1.0f;
    const int row = (warp < nrows) ? warp : warp - nrows;

    float2 x = *(float2*)&buf[(size_t)row*64 + lane*2];
    float sum = x.x + x.y;
    #pragma unroll
    for (int o = 16; o > 0; o >>= 1) sum += __shfl_xor_sync(0xffffffffu, sum, o);
    const float mean = sum * (1.0f/64.0f);
    const float dx = x.x - mean, dy = x.y - mean;
    float vs = dx*dx + dy*dy;
    #pragma unroll
    for (int o = 16; o > 0; o >>= 1) vs += __shfl_xor_sync(0xffffffffu, vs, o);
    const float inv = rsqrtf(vs * (1.0f/64.0f) + 1e-5f) * scale;
    float2 out; out.x = dx * inv; out.y = dy * inv;
    *(float2*)&buf[(size_t)row*64 + lane*2] = out;
}

// ---------------------------------------------------------------------------
// Flash attention, tf32 mma. One block = 64 q rows of one (b,h), 128 threads.
// K and V^T tiles in paired+XOR layout (pitch 64, conflict-free LDS.64):
//   word(row,k) = row*64 + ((k>>3)^(row&7))*8 + (k&3)*2 + ((k>>2)&1)
// P stays float (pitch FPT). Q smem aliases P smem.
// ---------------------------------------------------------------------------
#define FPT 68

__global__ __launch_bounds__(128, 3)
void flash_tf32()
{
    extern __shared__ char smemraw[];
    uint32_t* Ks = (uint32_t*)smemraw;        // [64*64] tf32 bits, paired layout
    uint32_t* Vt = Ks + 64*64;                // [64*64] V^T (row=d, col=key)
    float*    ps = (float*)(Vt + 64*64);      // [64][FPT] P (and Q at start)
    float*    qs = ps;

    const int bh    = blockIdx.y;
    const int qtile = blockIdx.x;
    const int b = bh / H_;
    const int h = bh - b * H_;

    const float* Q  = g_q + (size_t)bh * N_ * D_ + (size_t)qtile * 64 * D_;
    const float* Kp = g_k + (size_t)bh * N_ * D_;
    const float* Vp = g_v + (size_t)bh * N_ * D_;

    const int tid  = threadIdx.x;
    const int warp = tid >> 5, lane = tid & 31;
    const int g    = lane >> 2, tig = lane & 3;
    const int wband = warp * 16;

    // load q tile into qs (pitch FPT)
    for (int i = tid; i < 64*16; i += 128) {
        const int r = i >> 4, cv = (i & 15) << 2;
        *(float4*)&qs[r*FPT + cv] = *(const float4*)(Q + r*64 + cv);
    }
    __syncthreads();

    // hoist Q A-frags (tf32) — reused for all 16 KV tiles
    uint32_t qa[8][4];
    #pragma unroll
    for (int kf = 0; kf < 8; kf++) {
        const int r0 = wband + g;
        qa[kf][0] = f2tf(qs[ r0     *FPT + kf*8 + tig]);
        qa[kf][1] = f2tf(qs[(r0 + 8)*FPT + kf*8 + tig]);
        qa[kf][2] = f2tf(qs[ r0     *FPT + kf*8 + tig + 4]);
        qa[kf][3] = f2tf(qs[(r0 + 8)*FPT + kf*8 + tig + 4]);
    }

    // K loader mapping (one pass, 128 threads): row = tid>>1, 4 groups per thread
    const int krow = tid >> 1;
    const int khc  = (tid & 1) * 4;    // logical group offset 0 or 4
    const int kr7  = krow & 7;

    float o[8][4];
    #pragma unroll
    for (int nf = 0; nf < 8; nf++)
        #pragma unroll
        for (int e = 0; e < 4; e++) o[nf][e] = 0.f;
    float m0 = -1e30f, m1 = -1e30f, l0 = 0.f, l1 = 0.f;

    for (int j = 0; j < 16; j++) {
        __syncthreads();  // prior iter done with Ks/Vt; j=0: Q hoisted by all
        // K tile -> paired layout
        {
            const float* src = Kp + (size_t)j*4096 + krow*64 + khc*8;
            uint32_t* dstrow = Ks + krow*64;
            #pragma unroll
            for (int gi = 0; gi < 4; gi++) {
                const int lgk = khc + gi;
                float4 a  = *(const float4*)(src + gi*8);
                float4 b4 = *(const float4*)(src + gi*8 + 4);
                uint32_t* d = dstrow + ((lgk ^ kr7) << 3);
                *(uint4*)(d)     = make_uint4(f2tf(a.x), f2tf(b4.x), f2tf(a.y), f2tf(b4.y));
                *(uint4*)(d + 4) = make_uint4(f2tf(a.z), f2tf(b4.z), f2tf(a.w), f2tf(b4.w));
            }
        }
        // V tile -> transposed paired layout (row=d, col=key)
        for (int i = tid; i < 64*16; i += 128) {
            const int r = i >> 4, cv = (i & 15) << 2;   // key=r, d=cv..cv+3
            float4 v4 = *(const float4*)(Vp + (size_t)j*4096 + r*64 + cv);
            const int kf   = r >> 3;
            const int klow = ((r & 3) << 1) | ((r >> 2) & 1);
            Vt[(cv+0)*64 + ((kf ^ ((cv+0)&7)) << 3) + klow] = f2tf(v4.x);
            Vt[(cv+1)*64 + ((kf ^ ((cv+1)&7)) << 3) + klow] = f2tf(v4.y);
            Vt[(cv+2)*64 + ((kf ^ ((cv+2)&7)) << 3) + klow] = f2tf(v4.z);
            Vt[(cv+3)*64 + ((kf ^ ((cv+3)&7)) << 3) + klow] = f2tf(v4.w);
        }
        __syncthreads();

        // S = Q @ K^T   (warp: 16 rows x 64 cols)
        float s[8][4];
        #pragma unroll
        for (int nf = 0; nf < 8; nf++)
            #pragma unroll
            for (int e = 0; e < 4; e++) s[nf][e] = 0.f;

        #pragma unroll
        for (int kf = 0; kf < 8; kf++)
            #pragma unroll
            for (int nf = 0; nf < 8; nf++) {
                uint2 bb = *(const uint2*)(Ks + (nf*8 + g)*64 + ((kf ^ g) << 3) + tig*2);
                uint32_t bfr[2] = {bb.x, bb.y};
                mma8(s[nf], qa[kf], bfr);
            }

        // online softmax (rows r0 = wband+g, r1 = r0+8)
        float mx0 = -1e30f, mx1 = -1e30f;
        #pragma unroll
        for (int nf = 0; nf < 8; nf++) {
            mx0 = fmaxf(mx0, fmaxf(s[nf][0], s[nf][1]));
            mx1 = fmaxf(mx1, fmaxf(s[nf][2], s[nf][3]));
        }
        mx0 = fmaxf(mx0, __shfl_xor_sync(0xffffffffu, mx0, 1));
        mx0 = fmaxf(mx0, __shfl_xor_sync(0xffffffffu, mx0, 2));
        mx1 = fmaxf(mx1, __shfl_xor_sync(0xffffffffu, mx1, 1));
        mx1 = fmaxf(mx1, __shfl_xor_sync(0xffffffffu, mx1, 2));

        const float mn0 = fmaxf(m0, mx0);
        const float mn1 = fmaxf(m1, mx1);
        const float corr0 = __expf(m0 - mn0);
        const float corr1 = __expf(m1 - mn1);
        m0 = mn0; m1 = mn1;

        float rs0 = 0.f, rs1 = 0.f;
        #pragma unroll
        for (int nf = 0; nf < 8; nf++) {
            const float p0 = __expf(s[nf][0] - mn0);
            const float p1 = __expf(s[nf][1] - mn0);
            const float p2 = __expf(s[nf][2] - mn1);
            const float p3 = __expf(s[nf][3] - mn1);
            rs0 += p0 + p1;
            rs1 += p2 + p3;
            float2 w0; w0.x = p0; w0.y = p1;
            float2 w1; w1.x = p2; w1.y = p3;
            *(float2*)&ps[(wband + g    )*FPT + nf*8 + 2*tig] = w0;
            *(float2*)&ps[(wband + g + 8)*FPT + nf*8 + 2*tig] = w1;
        }
        rs0 += __shfl_xor_sync(0xffffffffu, rs0, 1);
        rs0 += __shfl_xor_sync(0xffffffffu, rs0, 2);
        rs1 += __shfl_xor_sync(0xffffffffu, rs1, 1);
        rs1 += __shfl_xor_sync(0xffffffffu, rs1, 2);
        l0 = l0 * corr0 + rs0;
        l1 = l1 * corr1 + rs1;

        #pragma unroll
        for (int nf = 0; nf < 8; nf++) {
            o[nf][0] *= corr0; o[nf][1] *= corr0;
            o[nf][2] *= corr1; o[nf][3] *= corr1;
        }
        __syncwarp();

        // O += P @ V
        #pragma unroll
        for (int kf = 0; kf < 8; kf++) {
            uint32_t pa[4];
            pa[0] = f2tf(ps[(wband + g    )*FPT + kf*8 + tig]);
            pa[1] = f2tf(ps[(wband + g + 8)*FPT + kf*8 + tig]);
            pa[2] = f2tf(ps[(wband + g    )*FPT + kf*8 + tig + 4]);
            pa[3] = f2tf(ps[(wband + g + 8)*FPT + kf*8 + tig + 4]);
            #pragma unroll
            for (int nf = 0; nf < 8; nf++) {
                uint2 bb = *(const uint2*)(Vt + (nf*8 + g)*64 + ((kf ^ g) << 3) + tig*2);
                uint32_t bv[2] = {bb.x, bb.y};
                mma8(o[nf], pa, bv);
            }
        }
        __syncwarp();  // ps reads done before next iter overwrites
    }

    // epilogue: O / l  -> g_ao [B,N,C], c = h*64 + d
    const float inv0 = 1.0f / l0;
    const float inv1 = 1.0f / l1;
    const int n0 = qtile*64 + wband + g;
    const int n1 = n0 + 8;
    #pragma unroll
    for (int nf = 0; nf < 8; nf++) {
        const int d = h*64 + nf*8 + 2*tig;
        float2 w0; w0.x = o[nf][0]*inv0; w0.y = o[nf][1]*inv0;
        float2 w1; w1.x = o[nf][2]*inv1; w1.y = o[nf][3]*inv1;
        *(float2*)&g_ao[((size_t)b*N_ + n0)*C_ + d] = w0;
        *(float2*)&g_ao[((size_t)b*N_ + n1)*C_ + d] = w1;
    }
}

// ---------------------------------------------------------------------------
extern "C" void kernel_launch(void* const* d_in, const int* in_sizes, int n_in,
                              void* d_out, int out_size)
{
    const float* x     = (const float*)d_in[0];   // [B,N,C]
    const float* wqkv  = (const float*)d_in[1];   // [3C,C]
    const float* wproj = (const float*)d_in[2];   // [C,C]
    float* out = (float*)d_out;                   // [B,N,C]

    // 1) QKV GEMM -> q/k/v [B,H,N,D]
    {
        dim3 grid(3*C_/128, (B_*N_)/128);   // (18, 64)
        gemm_tf32<0><<<grid, 256>>>(x, wqkv, nullptr, B_*N_, 3*C_, C_);
    }

    // 2) LayerNorm on q (*SCALE) and k
    {
        const int warps = 2 * BH_ * N_;
        const int blocks = (warps * 32 + 255) / 256;
        ln_kernel<<<blocks, 256>>>();
    }

    // 3) Flash attention -> g_ao
    {
        const int smem_bytes = (2*64*64)*(int)sizeof(uint32_t)
                             + (64*FPT)*(int)sizeof(float);   // 50176
        cudaFuncSetAttribute(flash_tf32,
                             cudaFuncAttributeMaxDynamicSharedMemorySize, smem_bytes);
        dim3 grid(N_/64, BH_);   // (16, 96)
        flash_tf32<<<grid, 128, smem_bytes>>>();
    }

    // 4) Output projection
    {
        dim3 grid(C_/128, (B_*N_)/128);     // (6, 64)
        gemm_tf32<1><<<grid, 256>>>(nullptr, wproj, out, B_*N_, C_, C_);
    }
}

// round 9
// speedup vs baseline: 1.4718x; 1.4718x over previous
#include <cuda_runtime.h>
#include <math.h>
#include <stdint.h>

#define B_ 8
#define N_ 1024
#define C_ 768
#define H_ 12
#define D_ 64
#define BH_ (B_*H_)

// Scratch (device globals — no allocation allowed)
__device__ float g_q [BH_*N_*D_];   // [B,H,N,D]
__device__ float g_k [BH_*N_*D_];
__device__ float g_v [BH_*N_*D_];
__device__ float g_ao[B_*N_*C_];    // attention output in [B,N,C]

// ---------------------------------------------------------------------------
// helpers
// ---------------------------------------------------------------------------
__device__ __forceinline__ uint32_t f2tf(float f) {
    uint32_t u;
    asm("cvt.rna.tf32.f32 %0, %1;" : "=r"(u) : "f"(f));
    return u;
}

__device__ __forceinline__ void mma8(float* c, const uint32_t* a, const uint32_t* b) {
    asm volatile(
        "mma.sync.aligned.m16n8k8.row.col.f32.tf32.tf32.f32 "
        "{%0,%1,%2,%3},{%4,%5,%6,%7},{%8,%9},{%0,%1,%2,%3};"
        : "+f"(c[0]), "+f"(c[1]), "+f"(c[2]), "+f"(c[3])
        : "r"(a[0]), "r"(a[1]), "r"(a[2]), "r"(a[3]), "r"(b[0]), "r"(b[1]));
}

__device__ __forceinline__ uint32_t smem_u32(const void* p) {
    uint32_t a;
    asm("{ .reg .u64 t; cvta.to.shared.u64 t, %1; cvt.u32.u64 %0, t; }"
        : "=r"(a) : "l"(p));
    return a;
}

// ldmatrix x4 over 32-bit words (tf32 fragments via b16 view)
__device__ __forceinline__ void ldsm4(uint32_t* r, uint32_t addr) {
    asm volatile("ldmatrix.sync.aligned.m8n8.x4.shared.b16 {%0,%1,%2,%3}, [%4];"
        : "=r"(r[0]), "=r"(r[1]), "=r"(r[2]), "=r"(r[3]) : "r"(addr));
}

// ---------------------------------------------------------------------------
// tf32 GEMM: Y[m,c] = sum_k A[m,k] * W[c,k]
// R6 structure (BM=BN=128, BK=16, 8 warps, warp 64x32, KP=20, pre-converted
// tf32 in smem). ONE change: fragments loaded via LDSM.x4 instead of LDS.32.
// MODE 0: scatter into g_q/g_k/g_v;  MODE 1: A := g_ao, row-major store.
// ---------------------------------------------------------------------------
#define KP 20

template<int MODE>
__global__ __launch_bounds__(256)
void gemm_tf32(const float* __restrict__ A, const float* __restrict__ W,
               float* __restrict__ Y, int M, int Ncol, int K)
{
    __shared__ uint32_t As[128*KP];
    __shared__ uint32_t Ws[128*KP];

    const int tid  = threadIdx.x;
    const int warp = tid >> 5, lane = tid & 31;
    const int g    = lane >> 2, tig = lane & 3;
    const int wm   = (warp >> 2) * 64;
    const int wn   = (warp & 3)  * 32;
    const int bm   = blockIdx.y * 128;
    const int bn   = blockIdx.x * 128;

    if (MODE == 1) A = g_ao;

    const int lr = tid >> 1;        // 0..127
    const int lc = (tid & 1) * 8;   // 0 or 8

    const float* Ap = A + (size_t)(bm + lr) * K + lc;
    const float* Wp = W + (size_t)(bn + lr) * K + lc;

    // LDSM per-lane row addresses (bytes):
    // A frag: lanes 0-15 -> rows (lane&15), col +0; lanes 16-31 -> rows, col +4
    // B frag x4 covers two n-tiles: lanes 0-7 rows 0-7 col 0; 8-15 rows 0-7 col 4;
    //                               16-23 rows 8-15 col 0; 24-31 rows 8-15 col 4
    const uint32_t a_lane = smem_u32(As)
        + (uint32_t)(((wm + (lane & 15)) * KP + ((lane >> 4) << 2)) * 4);
    const uint32_t b_lane = smem_u32(Ws)
        + (uint32_t)(((wn + (lane & 7) + ((lane >> 4) << 3)) * KP
                      + (((lane >> 3) & 1) << 2)) * 4);

    float acc[4][4][4];
    #pragma unroll
    for (int i = 0; i < 4; i++)
        #pragma unroll
        for (int j = 0; j < 4; j++)
            #pragma unroll
            for (int e = 0; e < 4; e++) acc[i][j][e] = 0.f;

    float4 ra0 = *(const float4*)Ap;
    float4 ra1 = *(const float4*)(Ap + 4);
    float4 rw0 = *(const float4*)Wp;
    float4 rw1 = *(const float4*)(Wp + 4);

    for (int k0 = 0; k0 < K; k0 += 16) {
        __syncthreads();
        {
            uint4 ua0 = make_uint4(f2tf(ra0.x), f2tf(ra0.y), f2tf(ra0.z), f2tf(ra0.w));
            uint4 ua1 = make_uint4(f2tf(ra1.x), f2tf(ra1.y), f2tf(ra1.z), f2tf(ra1.w));
            uint4 uw0 = make_uint4(f2tf(rw0.x), f2tf(rw0.y), f2tf(rw0.z), f2tf(rw0.w));
            uint4 uw1 = make_uint4(f2tf(rw1.x), f2tf(rw1.y), f2tf(rw1.z), f2tf(rw1.w));
            *(uint4*)&As[lr*KP + lc]     = ua0;
            *(uint4*)&As[lr*KP + lc + 4] = ua1;
            *(uint4*)&Ws[lr*KP + lc]     = uw0;
            *(uint4*)&Ws[lr*KP + lc + 4] = uw1;
        }
        __syncthreads();

        if (k0 + 16 < K) {
            Ap += 16; Wp += 16;
            ra0 = *(const float4*)Ap;
            ra1 = *(const float4*)(Ap + 4);
            rw0 = *(const float4*)Wp;
            rw1 = *(const float4*)(Wp + 4);
        }

        #pragma unroll
        for (int kk = 0; kk < 2; kk++) {
            const uint32_t kko = kk * 32;      // 8 words * 4B
            uint32_t af[4][4];
            #pragma unroll
            for (int mf = 0; mf < 4; mf++)
                ldsm4(af[mf], a_lane + (uint32_t)(mf*16*KP*4) + kko);
            uint32_t bf0[4], bf1[4];
            ldsm4(bf0, b_lane + kko);
            ldsm4(bf1, b_lane + (uint32_t)(16*KP*4) + kko);
            #pragma unroll
            for (int mf = 0; mf < 4; mf++) {
                mma8(acc[mf][0], af[mf], &bf0[0]);
                mma8(acc[mf][1], af[mf], &bf0[2]);
                mma8(acc[mf][2], af[mf], &bf1[0]);
                mma8(acc[mf][3], af[mf], &bf1[2]);
            }
        }
    }

    // epilogue
    #pragma unroll
    for (int mf = 0; mf < 4; mf++) {
        #pragma unroll
        for (int rr = 0; rr < 2; rr++) {
            const int m = bm + wm + mf*16 + g + rr*8;
            const int b = m >> 10;
            const int n = m & 1023;
            #pragma unroll
            for (int nf = 0; nf < 4; nf++) {
                const int c = bn + wn + nf*8 + 2*tig;
                float2 v2;
                v2.x = acc[mf][nf][rr*2 + 0];
                v2.y = acc[mf][nf][rr*2 + 1];
                if (MODE == 1) {
                    *(float2*)&Y[(size_t)m * Ncol + c] = v2;
                } else {
                    const int s = c / C_;
                    const int w = c - s * C_;
                    const int h = w >> 6;
                    const int d = w & 63;
                    const int idx = ((b*H_ + h)*N_ + n)*D_ + d;
                    if (s == 0)      *(float2*)&g_q[idx] = v2;
                    else if (s == 1) *(float2*)&g_k[idx] = v2;
                    else             *(float2*)&g_v[idx] = v2;
                }
            }
        }
    }
}

// ---------------------------------------------------------------------------
// Per-head LayerNorm over D=64. q rows also *SCALE (=1/8).
// ---------------------------------------------------------------------------
__global__ __launch_bounds__(256)
void ln_kernel()
{
    const int warp = (blockIdx.x * blockDim.x + threadIdx.x) >> 5;
    const int lane = threadIdx.x & 31;
    const int nrows = BH_ * N_;
    if (warp >= 2 * nrows) return;

    float* buf  = (warp < nrows) ? g_q : g_k;
    const float scale = (warp < nrows) ? 0.125f : 1.0f;
    const int row = (warp < nrows) ? warp : warp - nrows;

    float2 x = *(float2*)&buf[(size_t)row*64 + lane*2];
    float sum = x.x + x.y;
    #pragma unroll
    for (int o = 16; o > 0; o >>= 1) sum += __shfl_xor_sync(0xffffffffu, sum, o);
    const float mean = sum * (1.0f/64.0f);
    const float dx = x.x - mean, dy = x.y - mean;
    float vs = dx*dx + dy*dy;
    #pragma unroll
    for (int o = 16; o > 0; o >>= 1) vs += __shfl_xor_sync(0xffffffffu, vs, o);
    const float inv = rsqrtf(vs * (1.0f/64.0f) + 1e-5f) * scale;
    float2 out; out.x = dx * inv; out.y = dy * inv;
    *(float2*)&buf[(size_t)row*64 + lane*2] = out;
}

// ---------------------------------------------------------------------------
// Flash attention, tf32 mma (R6 layout, LDSM fragment loads).
// One block = 64 q rows of one (b,h), 128 threads.
// ---------------------------------------------------------------------------
#define FPT 68

__global__ __launch_bounds__(128, 3)
void flash_tf32()
{
    extern __shared__ char smemraw[];
    uint32_t* Ks = (uint32_t*)smemraw;        // [64][FPT] tf32 bits, K tile
    uint32_t* Vt = Ks + 64*FPT;               // [64][FPT] tf32 bits, V^T (row=d)
    float*    ps = (float*)(Vt + 64*FPT);     // [64][FPT] P (and Q at start)
    float*    qs = ps;

    const int bh    = blockIdx.y;
    const int qtile = blockIdx.x;
    const int b = bh / H_;
    const int h = bh - b * H_;

    const float* Q  = g_q + (size_t)bh * N_ * D_ + (size_t)qtile * 64 * D_;
    const float* Kp = g_k + (size_t)bh * N_ * D_;
    const float* Vp = g_v + (size_t)bh * N_ * D_;

    const int tid  = threadIdx.x;
    const int warp = tid >> 5, lane = tid & 31;
    const int g    = lane >> 2, tig = lane & 3;
    const int wband = warp * 16;

    // LDSM per-lane addresses
    const uint32_t bRowOff = (uint32_t)(((lane & 7) + ((lane >> 4) << 3)) * FPT
                                        + (((lane >> 3) & 1) << 2)) * 4;
    const uint32_t kb_lane = smem_u32(Ks) + bRowOff;
    const uint32_t vb_lane = smem_u32(Vt) + bRowOff;
    const uint32_t pa_lane = smem_u32(ps)
        + (uint32_t)(((wband + (lane & 15)) * FPT + ((lane >> 4) << 2)) * 4);

    // load q tile into qs (pitch FPT)
    for (int i = tid; i < 64*16; i += 128) {
        const int r = i >> 4, cv = (i & 15) << 2;
        *(float4*)&qs[r*FPT + cv] = *(const float4*)(Q + r*64 + cv);
    }
    __syncthreads();

    // hoist Q A-frags (tf32) — reused for all 16 KV tiles
    uint32_t qa[8][4];
    #pragma unroll
    for (int kf = 0; kf < 8; kf++) {
        uint32_t qraw[4];
        ldsm4(qraw, pa_lane + kf*32);
        qa[kf][0] = f2tf(__uint_as_float(qraw[0]));
        qa[kf][1] = f2tf(__uint_as_float(qraw[1]));
        qa[kf][2] = f2tf(__uint_as_float(qraw[2]));
        qa[kf][3] = f2tf(__uint_as_float(qraw[3]));
    }

    float o[8][4];
    #pragma unroll
    for (int nf = 0; nf < 8; nf++)
        #pragma unroll
        for (int e = 0; e < 4; e++) o[nf][e] = 0.f;
    float m0 = -1e30f, m1 = -1e30f, l0 = 0.f, l1 = 0.f;

    for (int j = 0; j < 16; j++) {
        __syncthreads();  // prior iter done with Ks/Vt; j=0: Q hoisted by all
        for (int i = tid; i < 64*16; i += 128) {
            const int r = i >> 4, cv = (i & 15) << 2;
            float4 k4 = *(const float4*)(Kp + (size_t)j*4096 + r*64 + cv);
            Ks[r*FPT + cv + 0] = f2tf(k4.x);
            Ks[r*FPT + cv + 1] = f2tf(k4.y);
            Ks[r*FPT + cv + 2] = f2tf(k4.z);
            Ks[r*FPT + cv + 3] = f2tf(k4.w);
            float4 v4 = *(const float4*)(Vp + (size_t)j*4096 + r*64 + cv);
            Vt[(cv+0)*FPT + r] = f2tf(v4.x);
            Vt[(cv+1)*FPT + r] = f2tf(v4.y);
            Vt[(cv+2)*FPT + r] = f2tf(v4.z);
            Vt[(cv+3)*FPT + r] = f2tf(v4.w);
        }
        __syncthreads();

        // S = Q @ K^T   (warp: 16 rows x 64 cols)
        float s[8][4];
        #pragma unroll
        for (int nf = 0; nf < 8; nf++)
            #pragma unroll
            for (int e = 0; e < 4; e++) s[nf][e] = 0.f;

        #pragma unroll
        for (int kf = 0; kf < 8; kf++) {
            uint32_t bfr[4][4];
            #pragma unroll
            for (int nfp = 0; nfp < 4; nfp++)
                ldsm4(bfr[nfp], kb_lane + (uint32_t)((nfp*16*FPT + kf*8) * 4));
            #pragma unroll
            for (int nf = 0; nf < 8; nf++)
                mma8(s[nf], qa[kf], &bfr[nf >> 1][(nf & 1) * 2]);
        }

        // online softmax (rows r0 = wband+g, r1 = r0+8)
        float mx0 = -1e30f, mx1 = -1e30f;
        #pragma unroll
        for (int nf = 0; nf < 8; nf++) {
            mx0 = fmaxf(mx0, fmaxf(s[nf][0], s[nf][1]));
            mx1 = fmaxf(mx1, fmaxf(s[nf][2], s[nf][3]));
        }
        mx0 = fmaxf(mx0, __shfl_xor_sync(0xffffffffu, mx0, 1));
        mx0 = fmaxf(mx0, __shfl_xor_sync(0xffffffffu, mx0, 2));
        mx1 = fmaxf(mx1, __shfl_xor_sync(0xffffffffu, mx1, 1));
        mx1 = fmaxf(mx1, __shfl_xor_sync(0xffffffffu, mx1, 2));

        const float mn0 = fmaxf(m0, mx0);
        const float mn1 = fmaxf(m1, mx1);
        const float corr0 = __expf(m0 - mn0);
        const float corr1 = __expf(m1 - mn1);
        m0 = mn0; m1 = mn1;

        float rs0 = 0.f, rs1 = 0.f;
        #pragma unroll
        for (int nf = 0; nf < 8; nf++) {
            const float p0 = __expf(s[nf][0] - mn0);
            const float p1 = __expf(s[nf][1] - mn0);
            const float p2 = __expf(s[nf][2] - mn1);
            const float p3 = __expf(s[nf][3] - mn1);
            rs0 += p0 + p1;
            rs1 += p2 + p3;
            float2 w0; w0.x = p0; w0.y = p1;
            float2 w1; w1.x = p2; w1.y = p3;
            *(float2*)&ps[(wband + g    )*FPT + nf*8 + 2*tig] = w0;
            *(float2*)&ps[(wband + g + 8)*FPT + nf*8 + 2*tig] = w1;
        }
        rs0 += __shfl_xor_sync(0xffffffffu, rs0, 1);
        rs0 += __shfl_xor_sync(0xffffffffu, rs0, 2);
        rs1 += __shfl_xor_sync(0xffffffffu, rs1, 1);
        rs1 += __shfl_xor_sync(0xffffffffu, rs1, 2);
        l0 = l0 * corr0 + rs0;
        l1 = l1 * corr1 + rs1;

        #pragma unroll
        for (int nf = 0; nf < 8; nf++) {
            o[nf][0] *= corr0; o[nf][1] *= corr0;
            o[nf][2] *= corr1; o[nf][3] *= corr1;
        }
        __syncwarp();

        // O += P @ V
        #pragma unroll
        for (int kf = 0; kf < 8; kf++) {
            uint32_t praw[4], pa[4];
            ldsm4(praw, pa_lane + kf*32);
            pa[0] = f2tf(__uint_as_float(praw[0]));
            pa[1] = f2tf(__uint_as_float(praw[1]));
            pa[2] = f2tf(__uint_as_float(praw[2]));
            pa[3] = f2tf(__uint_as_float(praw[3]));
            uint32_t bv[4][4];
            #pragma unroll
            for (int nfp = 0; nfp < 4; nfp++)
                ldsm4(bv[nfp], vb_lane + (uint32_t)((nfp*16*FPT + kf*8) * 4));
            #pragma unroll
            for (int nf = 0; nf < 8; nf++)
                mma8(o[nf], pa, &bv[nf >> 1][(nf & 1) * 2]);
        }
        __syncwarp();  // ps reads done before next iter overwrites
    }

    // epilogue: O / l  -> g_ao [B,N,C], c = h*64 + d
    const float inv0 = 1.0f / l0;
    const float inv1 = 1.0f / l1;
    const int n0 = qtile*64 + wband + g;
    const int n1 = n0 + 8;
    #pragma unroll
    for (int nf = 0; nf < 8; nf++) {
        const int d = h*64 + nf*8 + 2*tig;
        float2 w0; w0.x = o[nf][0]*inv0; w0.y = o[nf][1]*inv0;
        float2 w1; w1.x = o[nf][2]*inv1; w1.y = o[nf][3]*inv1;
        *(float2*)&g_ao[((size_t)b*N_ + n0)*C_ + d] = w0;
        *(float2*)&g_ao[((size_t)b*N_ + n1)*C_ + d] = w1;
    }
}

// ---------------------------------------------------------------------------
extern "C" void kernel_launch(void* const* d_in, const int* in_sizes, int n_in,
                              void* d_out, int out_size)
{
    const float* x     = (const float*)d_in[0];   // [B,N,C]
    const float* wqkv  = (const float*)d_in[1];   // [3C,C]
    const float* wproj = (const float*)d_in[2];   // [C,C]
    float* out = (float*)d_out;                   // [B,N,C]

    // 1) QKV GEMM -> q/k/v [B,H,N,D]
    {
        dim3 grid(3*C_/128, (B_*N_)/128);   // (18, 64)
        gemm_tf32<0><<<grid, 256>>>(x, wqkv, nullptr, B_*N_, 3*C_, C_);
    }

    // 2) LayerNorm on q (*SCALE) and k
    {
        const int warps = 2 * BH_ * N_;
        const int blocks = (warps * 32 + 255) / 256;
        ln_kernel<<<blocks, 256>>>();
    }

    // 3) Flash attention -> g_ao
    {
        const int smem_bytes = (2*64*FPT)*(int)sizeof(uint32_t)
                             + (64*FPT)*(int)sizeof(float);   // 52224
        cudaFuncSetAttribute(flash_tf32,
                             cudaFuncAttributeMaxDynamicSharedMemorySize, smem_bytes);
        dim3 grid(N_/64, BH_);   // (16, 96)
        flash_tf32<<<grid, 128, smem_bytes>>>();
    }

    // 4) Output projection
    {
        dim3 grid(C_/128, (B_*N_)/128);     // (6, 64)
        gemm_tf32<1><<<grid, 256>>>(nullptr, wproj, out, B_*N_, C_, C_);
    }
}

// round 10
// speedup vs baseline: 1.5104x; 1.0262x over previous
#include <cuda_runtime.h>
#include <math.h>
#include <stdint.h>

#define B_ 8
#define N_ 1024
#define C_ 768
#define H_ 12
#define D_ 64
#define BH_ (B_*H_)

// Scratch (device globals — no allocation allowed)
__device__ float g_q [BH_*N_*D_];   // [B,H,N,D]
__device__ float g_k [BH_*N_*D_];
__device__ float g_v [BH_*N_*D_];
__device__ float g_ao[B_*N_*C_];    // attention output in [B,N,C]

// ---------------------------------------------------------------------------
// helpers
// ---------------------------------------------------------------------------
__device__ __forceinline__ uint32_t f2tf(float f) {
    uint32_t u;
    asm("cvt.rna.tf32.f32 %0, %1;" : "=r"(u) : "f"(f));
    return u;
}

__device__ __forceinline__ void mma8(float* c, const uint32_t* a, const uint32_t* b) {
    asm volatile(
        "mma.sync.aligned.m16n8k8.row.col.f32.tf32.tf32.f32 "
        "{%0,%1,%2,%3},{%4,%5,%6,%7},{%8,%9},{%0,%1,%2,%3};"
        : "+f"(c[0]), "+f"(c[1]), "+f"(c[2]), "+f"(c[3])
        : "r"(a[0]), "r"(a[1]), "r"(a[2]), "r"(a[3]), "r"(b[0]), "r"(b[1]));
}

__device__ __forceinline__ uint32_t smem_u32(const void* p) {
    uint32_t a;
    asm("{ .reg .u64 t; cvta.to.shared.u64 t, %1; cvt.u32.u64 %0, t; }"
        : "=r"(a) : "l"(p));
    return a;
}

// ldmatrix x4 over 32-bit words (tf32 fragments via b16 view)
__device__ __forceinline__ void ldsm4(uint32_t* r, uint32_t addr) {
    asm volatile("ldmatrix.sync.aligned.m8n8.x4.shared.b16 {%0,%1,%2,%3}, [%4];"
        : "=r"(r[0]), "=r"(r[1]), "=r"(r[2]), "=r"(r[3]) : "r"(addr));
}

// ---------------------------------------------------------------------------
// tf32 GEMM: Y[m,c] = sum_k A[m,k] * W[c,k]
// R9 structure (BM=BN=128, BK=16, 8 warps, warp 64x32, KP=20, LDSM frags,
// pre-converted tf32 in smem). ONE change: double-buffered smem, single
// __syncthreads per k-slice (store i+1 / prefetch i+2 overlap compute i).
// MODE 0: scatter into g_q/g_k/g_v;  MODE 1: A := g_ao, row-major store.
// ---------------------------------------------------------------------------
#define KP 20
#define BUFW (128*KP)

template<int MODE>
__global__ __launch_bounds__(256)
void gemm_tf32(const float* __restrict__ A, const float* __restrict__ W,
               float* __restrict__ Y, int M, int Ncol, int K)
{
    __shared__ uint32_t As[2*BUFW];
    __shared__ uint32_t Ws[2*BUFW];

    const int tid  = threadIdx.x;
    const int warp = tid >> 5, lane = tid & 31;
    const int g    = lane >> 2, tig = lane & 3;
    const int wm   = (warp >> 2) * 64;
    const int wn   = (warp & 3)  * 32;
    const int bm   = blockIdx.y * 128;
    const int bn   = blockIdx.x * 128;

    if (MODE == 1) A = g_ao;

    const int lr = tid >> 1;        // 0..127
    const int lc = (tid & 1) * 8;   // 0 or 8

    const float* Ap = A + (size_t)(bm + lr) * K + lc;
    const float* Wp = W + (size_t)(bn + lr) * K + lc;

    // LDSM per-lane base addresses (buffer 0)
    const uint32_t a_lane = smem_u32(As)
        + (uint32_t)(((wm + (lane & 15)) * KP + ((lane >> 4) << 2)) * 4);
    const uint32_t b_lane = smem_u32(Ws)
        + (uint32_t)(((wn + (lane & 7) + ((lane >> 4) << 3)) * KP
                      + (((lane >> 3) & 1) << 2)) * 4);

    float acc[4][4][4];
    #pragma unroll
    for (int i = 0; i < 4; i++)
        #pragma unroll
        for (int j = 0; j < 4; j++)
            #pragma unroll
            for (int e = 0; e < 4; e++) acc[i][j][e] = 0.f;

    // slice 0 -> regs -> buf0
    float4 ra0 = *(const float4*)Ap;
    float4 ra1 = *(const float4*)(Ap + 4);
    float4 rw0 = *(const float4*)Wp;
    float4 rw1 = *(const float4*)(Wp + 4);
    {
        *(uint4*)&As[lr*KP + lc]     = make_uint4(f2tf(ra0.x), f2tf(ra0.y), f2tf(ra0.z), f2tf(ra0.w));
        *(uint4*)&As[lr*KP + lc + 4] = make_uint4(f2tf(ra1.x), f2tf(ra1.y), f2tf(ra1.z), f2tf(ra1.w));
        *(uint4*)&Ws[lr*KP + lc]     = make_uint4(f2tf(rw0.x), f2tf(rw0.y), f2tf(rw0.z), f2tf(rw0.w));
        *(uint4*)&Ws[lr*KP + lc + 4] = make_uint4(f2tf(rw1.x), f2tf(rw1.y), f2tf(rw1.z), f2tf(rw1.w));
    }
    // prefetch slice 1
    if (16 < K) {
        Ap += 16; Wp += 16;
        ra0 = *(const float4*)Ap;
        ra1 = *(const float4*)(Ap + 4);
        rw0 = *(const float4*)Wp;
        rw1 = *(const float4*)(Wp + 4);
    }
    __syncthreads();

    const int nk = K >> 4;
    for (int i = 0; i < nk; i++) {
        const int cur = i & 1;
        // store slice i+1 into other buffer
        if (i + 1 < nk) {
            uint32_t* da = As + (cur^1)*BUFW + lr*KP + lc;
            uint32_t* dw = Ws + (cur^1)*BUFW + lr*KP + lc;
            *(uint4*)(da)     = make_uint4(f2tf(ra0.x), f2tf(ra0.y), f2tf(ra0.z), f2tf(ra0.w));
            *(uint4*)(da + 4) = make_uint4(f2tf(ra1.x), f2tf(ra1.y), f2tf(ra1.z), f2tf(ra1.w));
            *(uint4*)(dw)     = make_uint4(f2tf(rw0.x), f2tf(rw0.y), f2tf(rw0.z), f2tf(rw0.w));
            *(uint4*)(dw + 4) = make_uint4(f2tf(rw1.x), f2tf(rw1.y), f2tf(rw1.z), f2tf(rw1.w));
        }
        // prefetch slice i+2
        if (i + 2 < nk) {
            Ap += 16; Wp += 16;
            ra0 = *(const float4*)Ap;
            ra1 = *(const float4*)(Ap + 4);
            rw0 = *(const float4*)Wp;
            rw1 = *(const float4*)(Wp + 4);
        }
        // compute buffer cur
        const uint32_t abuf = a_lane + cur*(BUFW*4);
        const uint32_t bbuf = b_lane + cur*(BUFW*4);
        #pragma unroll
        for (int kk = 0; kk < 2; kk++) {
            const uint32_t kko = kk * 32;      // 8 words * 4B
            uint32_t af[4][4];
            #pragma unroll
            for (int mf = 0; mf < 4; mf++)
                ldsm4(af[mf], abuf + (uint32_t)(mf*16*KP*4) + kko);
            uint32_t bf0[4], bf1[4];
            ldsm4(bf0, bbuf + kko);
            ldsm4(bf1, bbuf + (uint32_t)(16*KP*4) + kko);
            #pragma unroll
            for (int mf = 0; mf < 4; mf++) {
                mma8(acc[mf][0], af[mf], &bf0[0]);
                mma8(acc[mf][1], af[mf], &bf0[2]);
                mma8(acc[mf][2], af[mf], &bf1[0]);
                mma8(acc[mf][3], af[mf], &bf1[2]);
            }
        }
        __syncthreads();
    }

    // epilogue
    #pragma unroll
    for (int mf = 0; mf < 4; mf++) {
        #pragma unroll
        for (int rr = 0; rr < 2; rr++) {
            const int m = bm + wm + mf*16 + g + rr*8;
            const int b = m >> 10;
            const int n = m & 1023;
            #pragma unroll
            for (int nf = 0; nf < 4; nf++) {
                const int c = bn + wn + nf*8 + 2*tig;
                float2 v2;
                v2.x = acc[mf][nf][rr*2 + 0];
                v2.y = acc[mf][nf][rr*2 + 1];
                if (MODE == 1) {
                    *(float2*)&Y[(size_t)m * Ncol + c] = v2;
                } else {
                    const int s = c / C_;
                    const int w = c - s * C_;
                    const int h = w >> 6;
                    const int d = w & 63;
                    const int idx = ((b*H_ + h)*N_ + n)*D_ + d;
                    if (s == 0)      *(float2*)&g_q[idx] = v2;
                    else if (s == 1) *(float2*)&g_k[idx] = v2;
                    else             *(float2*)&g_v[idx] = v2;
                }
            }
        }
    }
}

// ---------------------------------------------------------------------------
// Per-head LayerNorm over D=64. q rows also *SCALE (=1/8).
// ---------------------------------------------------------------------------
__global__ __launch_bounds__(256)
void ln_kernel()
{
    const int warp = (blockIdx.x * blockDim.x + threadIdx.x) >> 5;
    const int lane = threadIdx.x & 31;
    const int nrows = BH_ * N_;
    if (warp >= 2 * nrows) return;

    float* buf  = (warp < nrows) ? g_q : g_k;
    const float scale = (warp < nrows) ? 0.125f : 1.0f;
    const int row = (warp < nrows) ? warp : warp - nrows;

    float2 x = *(float2*)&buf[(size_t)row*64 + lane*2];
    float sum = x.x + x.y;
    #pragma unroll
    for (int o = 16; o > 0; o >>= 1) sum += __shfl_xor_sync(0xffffffffu, sum, o);
    const float mean = sum * (1.0f/64.0f);
    const float dx = x.x - mean, dy = x.y - mean;
    float vs = dx*dx + dy*dy;
    #pragma unroll
    for (int o = 16; o > 0; o >>= 1) vs += __shfl_xor_sync(0xffffffffu, vs, o);
    const float inv = rsqrtf(vs * (1.0f/64.0f) + 1e-5f) * scale;
    float2 out; out.x = dx * inv; out.y = dy * inv;
    *(float2*)&buf[(size_t)row*64 + lane*2] = out;
}

// ---------------------------------------------------------------------------
// Flash attention, tf32 mma (R9 + P stored as tf32 bits).
// One block = 64 q rows of one (b,h), 128 threads.
// ---------------------------------------------------------------------------
#define FPT 68

__global__ __launch_bounds__(128, 3)
void flash_tf32()
{
    extern __shared__ char smemraw[];
    uint32_t* Ks  = (uint32_t*)smemraw;        // [64][FPT] tf32 bits, K tile
    uint32_t* Vt  = Ks + 64*FPT;               // [64][FPT] tf32 bits, V^T (row=d)
    uint32_t* psu = Vt + 64*FPT;               // [64][FPT] P tf32 bits (Q floats at start)
    float*    qs  = (float*)psu;

    const int bh    = blockIdx.y;
    const int qtile = blockIdx.x;
    const int b = bh / H_;
    const int h = bh - b * H_;

    const float* Q  = g_q + (size_t)bh * N_ * D_ + (size_t)qtile * 64 * D_;
    const float* Kp = g_k + (size_t)bh * N_ * D_;
    const float* Vp = g_v + (size_t)bh * N_ * D_;

    const int tid  = threadIdx.x;
    const int warp = tid >> 5, lane = tid & 31;
    const int g    = lane >> 2, tig = lane & 3;
    const int wband = warp * 16;

    // LDSM per-lane addresses
    const uint32_t bRowOff = (uint32_t)(((lane & 7) + ((lane >> 4) << 3)) * FPT
                                        + (((lane >> 3) & 1) << 2)) * 4;
    const uint32_t kb_lane = smem_u32(Ks) + bRowOff;
    const uint32_t vb_lane = smem_u32(Vt) + bRowOff;
    const uint32_t pa_lane = smem_u32(psu)
        + (uint32_t)(((wband + (lane & 15)) * FPT + ((lane >> 4) << 2)) * 4);

    // load q tile (floats) into psu-aliased qs (pitch FPT)
    for (int i = tid; i < 64*16; i += 128) {
        const int r = i >> 4, cv = (i & 15) << 2;
        *(float4*)&qs[r*FPT + cv] = *(const float4*)(Q + r*64 + cv);
    }
    __syncthreads();

    // hoist Q A-frags (tf32) — reused for all 16 KV tiles
    uint32_t qa[8][4];
    #pragma unroll
    for (int kf = 0; kf < 8; kf++) {
        uint32_t qraw[4];
        ldsm4(qraw, pa_lane + kf*32);
        qa[kf][0] = f2tf(__uint_as_float(qraw[0]));
        qa[kf][1] = f2tf(__uint_as_float(qraw[1]));
        qa[kf][2] = f2tf(__uint_as_float(qraw[2]));
        qa[kf][3] = f2tf(__uint_as_float(qraw[3]));
    }

    float o[8][4];
    #pragma unroll
    for (int nf = 0; nf < 8; nf++)
        #pragma unroll
        for (int e = 0; e < 4; e++) o[nf][e] = 0.f;
    float m0 = -1e30f, m1 = -1e30f, l0 = 0.f, l1 = 0.f;

    for (int j = 0; j < 16; j++) {
        __syncthreads();  // prior iter done with Ks/Vt; j=0: Q hoisted by all
        for (int i = tid; i < 64*16; i += 128) {
            const int r = i >> 4, cv = (i & 15) << 2;
            float4 k4 = *(const float4*)(Kp + (size_t)j*4096 + r*64 + cv);
            Ks[r*FPT + cv + 0] = f2tf(k4.x);
            Ks[r*FPT + cv + 1] = f2tf(k4.y);
            Ks[r*FPT + cv + 2] = f2tf(k4.z);
            Ks[r*FPT + cv + 3] = f2tf(k4.w);
            float4 v4 = *(const float4*)(Vp + (size_t)j*4096 + r*64 + cv);
            Vt[(cv+0)*FPT + r] = f2tf(v4.x);
            Vt[(cv+1)*FPT + r] = f2tf(v4.y);
            Vt[(cv+2)*FPT + r] = f2tf(v4.z);
            Vt[(cv+3)*FPT + r] = f2tf(v4.w);
        }
        __syncthreads();

        // S = Q @ K^T   (warp: 16 rows x 64 cols)
        float s[8][4];
        #pragma unroll
        for (int nf = 0; nf < 8; nf++)
            #pragma unroll
            for (int e = 0; e < 4; e++) s[nf][e] = 0.f;

        #pragma unroll
        for (int kf = 0; kf < 8; kf++) {
            uint32_t bfr[4][4];
            #pragma unroll
            for (int nfp = 0; nfp < 4; nfp++)
                ldsm4(bfr[nfp], kb_lane + (uint32_t)((nfp*16*FPT + kf*8) * 4));
            #pragma unroll
            for (int nf = 0; nf < 8; nf++)
                mma8(s[nf], qa[kf], &bfr[nf >> 1][(nf & 1) * 2]);
        }

        // online softmax (rows r0 = wband+g, r1 = r0+8)
        float mx0 = -1e30f, mx1 = -1e30f;
        #pragma unroll
        for (int nf = 0; nf < 8; nf++) {
            mx0 = fmaxf(mx0, fmaxf(s[nf][0], s[nf][1]));
            mx1 = fmaxf(mx1, fmaxf(s[nf][2], s[nf][3]));
        }
        mx0 = fmaxf(mx0, __shfl_xor_sync(0xffffffffu, mx0, 1));
        mx0 = fmaxf(mx0, __shfl_xor_sync(0xffffffffu, mx0, 2));
        mx1 = fmaxf(mx1, __shfl_xor_sync(0xffffffffu, mx1, 1));
        mx1 = fmaxf(mx1, __shfl_xor_sync(0xffffffffu, mx1, 2));

        const float mn0 = fmaxf(m0, mx0);
        const float mn1 = fmaxf(m1, mx1);
        const float corr0 = __expf(m0 - mn0);
        const float corr1 = __expf(m1 - mn1);
        m0 = mn0; m1 = mn1;

        float rs0 = 0.f, rs1 = 0.f;
        #pragma unroll
        for (int nf = 0; nf < 8; nf++) {
            const float p0 = __expf(s[nf][0] - mn0);
            const float p1 = __expf(s[nf][1] - mn0);
            const float p2 = __expf(s[nf][2] - mn1);
            const float p3 = __expf(s[nf][3] - mn1);
            rs0 += p0 + p1;
            rs1 += p2 + p3;
            // store P as tf32 bits (kills cvt on the PV critical path)
            *(uint2*)&psu[(wband + g    )*FPT + nf*8 + 2*tig] =
                make_uint2(f2tf(p0), f2tf(p1));
            *(uint2*)&psu[(wband + g + 8)*FPT + nf*8 + 2*tig] =
                make_uint2(f2tf(p2), f2tf(p3));
        }
        rs0 += __shfl_xor_sync(0xffffffffu, rs0, 1);
        rs0 += __shfl_xor_sync(0xffffffffu, rs0, 2);
        rs1 += __shfl_xor_sync(0xffffffffu, rs1, 1);
        rs1 += __shfl_xor_sync(0xffffffffu, rs1, 2);
        l0 = l0 * corr0 + rs0;
        l1 = l1 * corr1 + rs1;

        #pragma unroll
        for (int nf = 0; nf < 8; nf++) {
            o[nf][0] *= corr0; o[nf][1] *= corr0;
            o[nf][2] *= corr1; o[nf][3] *= corr1;
        }
        __syncwarp();

        // O += P @ V
        #pragma unroll
        for (int kf = 0; kf < 8; kf++) {
            uint32_t pa[4];
            ldsm4(pa, pa_lane + kf*32);        // already tf32 bits
            uint32_t bv[4][4];
            #pragma unroll
            for (int nfp = 0; nfp < 4; nfp++)
                ldsm4(bv[nfp], vb_lane + (uint32_t)((nfp*16*FPT + kf*8) * 4));
            #pragma unroll
            for (int nf = 0; nf < 8; nf++)
                mma8(o[nf], pa, &bv[nf >> 1][(nf & 1) * 2]);
        }
        __syncwarp();  // psu reads done before next iter overwrites
    }

    // epilogue: O / l  -> g_ao [B,N,C], c = h*64 + d
    const float inv0 = 1.0f / l0;
    const float inv1 = 1.0f / l1;
    const int n0 = qtile*64 + wband + g;
    const int n1 = n0 + 8;
    #pragma unroll
    for (int nf = 0; nf < 8; nf++) {
        const int d = h*64 + nf*8 + 2*tig;
        float2 w0; w0.x = o[nf][0]*inv0; w0.y = o[nf][1]*inv0;
        float2 w1; w1.x = o[nf][2]*inv1; w1.y = o[nf][3]*inv1;
        *(float2*)&g_ao[((size_t)b*N_ + n0)*C_ + d] = w0;
        *(float2*)&g_ao[((size_t)b*N_ + n1)*C_ + d] = w1;
    }
}

// ---------------------------------------------------------------------------
extern "C" void kernel_launch(void* const* d_in, const int* in_sizes, int n_in,
                              void* d_out, int out_size)
{
    const float* x     = (const float*)d_in[0];   // [B,N,C]
    const float* wqkv  = (const float*)d_in[1];   // [3C,C]
    const float* wproj = (const float*)d_in[2];   // [C,C]
    float* out = (float*)d_out;                   // [B,N,C]

    // 1) QKV GEMM -> q/k/v [B,H,N,D]
    {
        dim3 grid(3*C_/128, (B_*N_)/128);   // (18, 64)
        gemm_tf32<0><<<grid, 256>>>(x, wqkv, nullptr, B_*N_, 3*C_, C_);
    }

    // 2) LayerNorm on q (*SCALE) and k
    {
        const int warps = 2 * BH_ * N_;
        const int blocks = (warps * 32 + 255) / 256;
        ln_kernel<<<blocks, 256>>>();
    }

    // 3) Flash attention -> g_ao
    {
        const int smem_bytes = (3*64*FPT)*(int)sizeof(uint32_t);   // 52224
        cudaFuncSetAttribute(flash_tf32,
                             cudaFuncAttributeMaxDynamicSharedMemorySize, smem_bytes);
        dim3 grid(N_/64, BH_);   // (16, 96)
        flash_tf32<<<grid, 128, smem_bytes>>>();
    }

    // 4) Output projection
    {
        dim3 grid(C_/128, (B_*N_)/128);     // (6, 64)
        gemm_tf32<1><<<grid, 256>>>(nullptr, wproj, out, B_*N_, C_, C_);
    }
}